// round 17
// baseline (speedup 1.0000x reference)
#include <cuda_runtime.h>
#include <math.h>

#define SEQ  1024
#define NF   256
#define H    1024
#define G4   4096
#define OUTN 1024
#define NB   128
#define JPB  8
#define NCTRS 16                 // arrival counters per step (own 128B line each)
#define TARGET 64                // 8 CTAs x 8 warps arrive per counter

typedef unsigned long long u64;

__device__ float    g_gx[(size_t)SEQ * G4];
__device__ float    g_h[(size_t)(SEQ + 1) * H];   // row 0 never read (t=0 uses literal zeros)
__device__ float    g_logits[(size_t)SEQ * OUTN];
__device__ float    g_lse[SEQ];
__device__ u64      g_sorted[(size_t)SEQ * OUTN];
__device__ unsigned g_done[(size_t)(SEQ + 1) * NCTRS * 32];   // memset per launch

__device__ __forceinline__ float sigm(float x) { return 1.0f / (1.0f + __expf(-x)); }

__device__ __forceinline__ unsigned ld_rlx(const unsigned* p) {
    unsigned v;
    asm volatile("ld.relaxed.gpu.global.u32 %0, [%1];" : "=r"(v) : "l"(p) : "memory");
    return v;
}
__device__ __forceinline__ void red_rel(unsigned* p) {
    asm volatile("red.release.gpu.global.add.u32 [%0], 1;" :: "l"(p) : "memory");
}
__device__ __forceinline__ void fence_acq_rel_gpu() {
    asm volatile("fence.acq_rel.gpu;" ::: "memory");
}
__device__ __forceinline__ unsigned* done_ctr(int step, int c) {
    return &g_done[((size_t)step * NCTRS + c) * 32];
}
__device__ __forceinline__ float dot4(float4 a, float4 b) {
    return a.x * b.x + a.y * b.y + a.z * b.z + a.w * b.w;
}

// ---------------- Kernel A: gx[t][r] = b_ih[r]+b_hh[r] + X[t]·W_ih[r] ----------------
__global__ void precompute_gx(const float* __restrict__ X,
                              const float* __restrict__ Wih,
                              const float* __restrict__ bih,
                              const float* __restrict__ bhh) {
    __shared__ float Xs[32 * NF];
    const int r  = blockIdx.x * 256 + threadIdx.x;
    const int t0 = blockIdx.y * 32;

    for (int i = threadIdx.x; i < 32 * NF; i += 256)
        Xs[i] = X[(size_t)t0 * NF + i];
    __syncthreads();

    const float bias = bih[r] + bhh[r];
    float acc[32];
#pragma unroll
    for (int tt = 0; tt < 32; tt++) acc[tt] = bias;

    const float4* Wr = (const float4*)(Wih + (size_t)r * NF);
    for (int k4 = 0; k4 < NF / 4; k4++) {
        float4 wv = Wr[k4];
#pragma unroll
        for (int tt = 0; tt < 32; tt++)
            acc[tt] += dot4(wv, *(const float4*)&Xs[tt * NF + k4 * 4]);
    }
#pragma unroll
    for (int tt = 0; tt < 32; tt++)
        g_gx[(size_t)(t0 + tt) * G4 + r] = acc[tt];
}

// ---------------- Kernel B: warp-autonomous persistent LSTM (no CTA barriers) ----------
// Warp w owns j=b*8+w completely: 4 gate rows x 1024 cols in 32 float4 regs.
// Warp 0 polls the 16 global counters (1 round), raises smem flag; others spin on LDS.
__global__ void __launch_bounds__(256, 1)
lstm_recurrence(const float* __restrict__ enc,
                const float* __restrict__ Whh) {
    __shared__ unsigned sflag;

    const int b = blockIdx.x, tid = threadIdx.x;
    const int w = tid >> 5, l = tid & 31;
    const int j = b * JPB + w;
    const int myctr = b >> 3;

    if (tid == 0) sflag = 0;

    // ---- Whh rows of j into registers (coalesced lane-stride float4) ----
    float4 wh[32];
    const float4* Whh4 = (const float4*)Whh;
#pragma unroll
    for (int g = 0; g < 4; g++)
#pragma unroll
        for (int k = 0; k < 8; k++)
            wh[g * 8 + k] = Whh4[(size_t)(g * H + j) * 256 + k * 32 + l];

    const float c0j = enc[(size_t)(SEQ - 1) * H + j];
    float gxv = (l < 4) ? g_gx[(size_t)0 * G4 + l * H + j] : 0.f;   // t=0 prefetch
    __syncthreads();   // sflag init visible (only barrier; outside the loop)

    for (int t = 0; t < SEQ; t++) {
        float a0 = 0.f, a1 = 0.f, a2 = 0.f, a3 = 0.f;

        if (t > 0) {
            // ---- detect h_t ready ----
            if (w == 0) {
                for (;;) {
                    unsigned v = TARGET;
                    if (l < NCTRS) v = ld_rlx(done_ctr(t, l));
                    if (__all_sync(0xffffffffu, v >= TARGET)) break;
                }
                fence_acq_rel_gpu();
                __syncwarp();
                if (l == 0) *(volatile unsigned*)&sflag = (unsigned)t;
            } else {
                while (*(volatile unsigned*)&sflag < (unsigned)t) {}
                fence_acq_rel_gpu();
            }

            // ---- full 1024-dot from register weights ----
            const float4* hp = (const float4*)(g_h + (size_t)t * H);
#pragma unroll
            for (int k = 0; k < 8; k++) {
                float4 hv = hp[k * 32 + l];
                a0 += dot4(wh[k],      hv);
                a1 += dot4(wh[8 + k],  hv);
                a2 += dot4(wh[16 + k], hv);
                a3 += dot4(wh[24 + k], hv);
            }
        }

#pragma unroll
        for (int off = 16; off; off >>= 1) {
            a0 += __shfl_down_sync(0xffffffffu, a0, off);
            a1 += __shfl_down_sync(0xffffffffu, a1, off);
            a2 += __shfl_down_sync(0xffffffffu, a2, off);
            a3 += __shfl_down_sync(0xffffffffu, a3, off);
        }
        float gx0 = __shfl_sync(0xffffffffu, gxv, 0);
        float gx1 = __shfl_sync(0xffffffffu, gxv, 1);
        float gx2 = __shfl_sync(0xffffffffu, gxv, 2);
        float gx3 = __shfl_sync(0xffffffffu, gxv, 3);

        if (l == 0) {
            float ig = sigm(a0 + gx0);
            float fg = sigm(a1 + gx1);
            float gg = tanhf(a2 + gx2);
            float og = sigm(a3 + gx3);
            float c  = fg * c0j + ig * gg;
            g_h[(size_t)(t + 1) * H + j] = og * tanhf(c);
            red_rel(done_ctr(t + 1, myctr));     // release orders the h store
        }

        if (t + 1 < SEQ && l < 4)
            gxv = g_gx[(size_t)(t + 1) * G4 + l * H + j];   // prefetch (off critical path)
    }
    // logits are produced by logits_gemm after this kernel (kernel-boundary sync)
}

// ---------------- Kernel G: logits[t][j] = h[t+1]·Wout[j] + bout[j] (1024^3 GEMM) ----
__global__ void logits_gemm(const float* __restrict__ Wout,
                            const float* __restrict__ bout) {
    __shared__ float Hs[32 * 128];
    const int tid  = threadIdx.x;
    const int jrow = blockIdx.x * 256 + tid;    // gridDim.x = 4
    const int t0   = blockIdx.y * 32;           // gridDim.y = 32

    const float bias = bout[jrow];
    float acc[32];
#pragma unroll
    for (int tt = 0; tt < 32; tt++) acc[tt] = bias;

    for (int cb = 0; cb < 8; cb++) {
        __syncthreads();
        for (int i = tid; i < 32 * 128; i += 256) {
            int tt = i >> 7, cc = i & 127;
            Hs[i] = g_h[(size_t)(t0 + tt + 1) * H + cb * 128 + cc];
        }
        __syncthreads();
        const float4* Wr = (const float4*)(Wout + (size_t)jrow * H + cb * 128);
#pragma unroll 8
        for (int k4 = 0; k4 < 32; k4++) {
            float4 wv = Wr[k4];
#pragma unroll
            for (int tt = 0; tt < 32; tt++)
                acc[tt] += dot4(wv, *(const float4*)&Hs[tt * 128 + k4 * 4]);
        }
    }
#pragma unroll
    for (int tt = 0; tt < 32; tt++)
        g_logits[(size_t)(t0 + tt) * OUTN + jrow] = acc[tt];
}

// ---------------- Kernel C: per-row logsumexp ----------------
__global__ void row_lse() {
    const int t = blockIdx.x, tid = threadIdx.x, w = tid >> 5, l = tid & 31;
    __shared__ float red[8];
    float v[4];
#pragma unroll
    for (int k = 0; k < 4; k++) v[k] = g_logits[(size_t)t * OUTN + tid + k * 256];
    float m = fmaxf(fmaxf(v[0], v[1]), fmaxf(v[2], v[3]));
#pragma unroll
    for (int off = 16; off; off >>= 1) m = fmaxf(m, __shfl_xor_sync(0xffffffffu, m, off));
    if (l == 0) red[w] = m;
    __syncthreads();
    float M = red[0];
#pragma unroll
    for (int i = 1; i < 8; i++) M = fmaxf(M, red[i]);
    float s = 0.f;
#pragma unroll
    for (int k = 0; k < 4; k++) s += expf(v[k] - M);
#pragma unroll
    for (int off = 16; off; off >>= 1) s += __shfl_xor_sync(0xffffffffu, s, off);
    __syncthreads();
    if (l == 0) red[w] = s;
    __syncthreads();
    if (tid == 0) {
        float S = 0.f;
#pragma unroll
        for (int i = 0; i < 8; i++) S += red[i];
        g_lse[t] = M + logf(S);
    }
}

// ---------------- Kernel S: bitonic sort rows (descending u64 keys) ----------------
__global__ void sort_rows() {
    __shared__ u64 key[OUTN];
    const int t = blockIdx.x, tid = threadIdx.x;

    for (int i = tid; i < OUTN; i += 256) {
        unsigned u = __float_as_uint(g_logits[(size_t)t * OUTN + i]);
        unsigned m = (u & 0x80000000u) ? ~u : (u | 0x80000000u);
        key[i] = ((u64)m << 32) | (u64)(OUTN - 1 - i);
    }
    __syncthreads();

    for (int k = 2; k <= OUTN; k <<= 1) {
        for (int jj = k >> 1; jj > 0; jj >>= 1) {
            for (int i = tid; i < OUTN; i += 256) {
                int ix = i ^ jj;
                if (ix > i) {
                    bool descend = (i & k) == 0;
                    u64 a = key[i], c = key[ix];
                    bool sw = descend ? (a < c) : (a > c);
                    if (sw) { key[i] = c; key[ix] = a; }
                }
            }
            __syncthreads();
        }
    }

    for (int i = tid; i < OUTN; i += 256)
        g_sorted[(size_t)t * OUTN + i] = key[i];
}

// ---------------- Kernel D: ballot tour selection over sorted candidates ----------------
__global__ void tour_select(float* __restrict__ out, int out_size) {
    __shared__ unsigned vis[32];
    const int l = threadIdx.x;
    vis[l] = 0;
    __syncwarp();

    u64 cur = g_sorted[l];
    float lse_c = g_lse[0];

    for (int t = 0; t < SEQ; t++) {
        u64 nxt = 0; float lse_n = 0.f;
        if (t + 1 < SEQ) {
            nxt   = g_sorted[(size_t)(t + 1) * OUTN + l];
            lse_n = g_lse[t + 1];
        }

        u64 key = cur;
        int batch = 0;
        unsigned ballot;
        for (;;) {
            unsigned idx = OUTN - 1 - (unsigned)(key & 0xFFFFFFFFu);
            bool unvis = ((vis[idx >> 5] >> (idx & 31)) & 1u) == 0u;
            ballot = __ballot_sync(0xffffffffu, unvis);
            if (ballot) break;
            batch++;
            key = g_sorted[(size_t)t * OUTN + batch * 32 + l];
        }
        int wl = __ffs(ballot) - 1;
        u64 wkey = __shfl_sync(0xffffffffu, key, wl);
        unsigned widx = OUTN - 1 - (unsigned)(wkey & 0xFFFFFFFFu);
        if (l == 0) {
            unsigned m = (unsigned)(wkey >> 32);
            unsigned u = (m & 0x80000000u) ? (m ^ 0x80000000u) : ~m;
            float val = __uint_as_float(u);
            if (t < out_size)       out[t] = (float)widx;
            if (SEQ + t < out_size) out[SEQ + t] = val - lse_c;
            vis[widx >> 5] |= 1u << (widx & 31);
        }
        __syncwarp();

        cur = nxt; lse_c = lse_n;
    }
}

// ---------------- launch ----------------
extern "C" void kernel_launch(void* const* d_in, const int* in_sizes, int n_in,
                              void* d_out, int out_size) {
    const float* X    = (const float*)d_in[0];
    const float* enc  = (const float*)d_in[1];
    const float* Wih  = (const float*)d_in[2];
    const float* Whh  = (const float*)d_in[3];
    const float* bih  = (const float*)d_in[4];
    const float* bhh  = (const float*)d_in[5];
    const float* Wout = (const float*)d_in[6];
    const float* bout = (const float*)d_in[7];
    float* out = (float*)d_out;

    // per-launch counter reset (graph memset node — execution proven by R14/R15 replays)
    void* doneAddr = nullptr; cudaGetSymbolAddress(&doneAddr, g_done);
    cudaMemsetAsync(doneAddr, 0, (size_t)(SEQ + 1) * NCTRS * 32 * sizeof(unsigned));

    precompute_gx<<<dim3(16, 32), 256>>>(X, Wih, bih, bhh);
    lstm_recurrence<<<NB, 256>>>(enc, Whh);
    logits_gemm<<<dim3(4, 32), 256>>>(Wout, bout);
    row_lse<<<SEQ, 256>>>();
    sort_rows<<<SEQ, 256>>>();
    tour_select<<<1, 32>>>(out, out_size);
}